// round 10
// baseline (speedup 1.0000x reference)
#include <cuda_runtime.h>
#include <cuda_fp16.h>
#include <cstdint>

#define M_TOK   8192
#define DIN     4096
#define DOUT    4096
#define RNK     64
#define NEXP    16
#define KG      1024
#define KTOT    5120
#define SCALING 0.5f

// ---------------- scratch (static device globals; no allocations) -----------
__device__ __half g_xg[(size_t)M_TOK * KTOT];   // 80 MB  [x | g] fp16, row-major
__device__ __half g_wt[(size_t)DOUT * KTOT];    // 40 MB  [base_w | B_flat] fp16
__device__ __half g_w2[128 * DIN];              //  1 MB  [A; router_w; 0] fp16
__device__ float  g_hl[4 * M_TOK * 128];        // 16 MB  split-K partials (4 planes)

// ---------------- helpers ----------------------------------------------------
__device__ __forceinline__ uint32_t smem_u32(const void* p) {
    return (uint32_t)__cvta_generic_to_shared(p);
}
__device__ __forceinline__ uint32_t pack2h(__half a, __half b) {
    return (uint32_t)__half_as_ushort(a) | ((uint32_t)__half_as_ushort(b) << 16);
}

// ---------------- conversion kernels -----------------------------------------
__global__ void convert_x_kernel(const float4* __restrict__ x4) {
    int i = blockIdx.x * blockDim.x + threadIdx.x;      // < M_TOK*DIN/4
    float4 v = x4[i];
    int e = i << 2;
    int row = e >> 12, col = e & (DIN - 1);
    *(uint2*)(g_xg + (size_t)row * KTOT + col) =
        make_uint2(pack2h(__float2half_rn(v.x), __float2half_rn(v.y)),
                   pack2h(__float2half_rn(v.z), __float2half_rn(v.w)));
}

__global__ void prep_w_kernel(const float* __restrict__ bw, const float* __restrict__ Bm) {
    int i = blockIdx.x * blockDim.x + threadIdx.x;      // < DOUT*KTOT/4
    int e = i << 2;
    int o = e / KTOT, k = e - o * KTOT;
    float4 v;
    if (k < DIN) {
        v = *(const float4*)(bw + (size_t)o * DIN + k);
    } else {
        int kk = k - DIN, ei = kk >> 6, r = kk & 63;
        v = *(const float4*)(Bm + ((size_t)(ei * DOUT + o) * RNK + r));
    }
    *(uint2*)(g_wt + (size_t)o * KTOT + k) =
        make_uint2(pack2h(__float2half_rn(v.x), __float2half_rn(v.y)),
                   pack2h(__float2half_rn(v.z), __float2half_rn(v.w)));
}

__global__ void prep_w2_kernel(const float* __restrict__ Am, const float* __restrict__ rw) {
    int i = blockIdx.x * blockDim.x + threadIdx.x;      // < 128*DIN/4
    int e = i << 2;
    int r = e >> 12, k = e & (DIN - 1);
    float4 v = make_float4(0.f, 0.f, 0.f, 0.f);
    if (r < 64)      v = *(const float4*)(Am + (size_t)r * DIN + k);
    else if (r < 80) v = *(const float4*)(rw + (size_t)(r - 64) * DIN + k);
    *(uint2*)(g_w2 + (size_t)r * DIN + k) =
        make_uint2(pack2h(__float2half_rn(v.x), __float2half_rn(v.y)),
                   pack2h(__float2half_rn(v.z), __float2half_rn(v.w)));
}

// ---------------- router: softmax/top2 -> g columns of g_xg -------------------
__global__ void router_kernel() {
    int warp = threadIdx.x >> 5, lane = threadIdx.x & 31;
    int t = blockIdx.x * 8 + warp;
    __shared__ float wsel[8][16];
    const float* p0 = g_hl + (size_t)t * 128;
    const float* p1 = p0 + (size_t)M_TOK * 128;
    const float* p2 = p1 + (size_t)M_TOK * 128;
    const float* p3 = p2 + (size_t)M_TOK * 128;
    if (lane == 0) {
        float lg[16]; float m = -1e30f;
        #pragma unroll
        for (int e = 0; e < 16; e++) {
            lg[e] = p0[64 + e] + p1[64 + e] + p2[64 + e] + p3[64 + e];
            m = fmaxf(m, lg[e]);
        }
        float p[16], Z = 0.f;
        #pragma unroll
        for (int e = 0; e < 16; e++) { p[e] = expf(lg[e] - m); Z += p[e]; }
        float inv = 1.f / Z;
        int i1 = 0; float b1 = -1.f;
        #pragma unroll
        for (int e = 0; e < 16; e++) if (p[e] > b1) { b1 = p[e]; i1 = e; }
        int i2 = 0; float b2 = -1.f;
        #pragma unroll
        for (int e = 0; e < 16; e++) if (e != i1 && p[e] > b2) { b2 = p[e]; i2 = e; }
        b1 *= inv; b2 *= inv;
        float den = b1 + b2 + 1e-6f;
        #pragma unroll
        for (int e = 0; e < 16; e++) wsel[warp][e] = 0.f;
        wsel[warp][i1] = (b1 / den) * SCALING;
        wsel[warp][i2] = (b2 / den) * SCALING;
    }
    __syncwarp();
    __half* grow = g_xg + (size_t)t * KTOT + DIN;
    for (int c = lane; c < KG; c += 32) {
        float v = wsel[warp][c >> 6] * (p0[c & 63] + p1[c & 63] + p2[c & 63] + p3[c & 63]);
        grow[c] = __float2half_rn(v);
    }
}

// ---------------- common GEMM macros ------------------------------------------
#define LDT     40                          // 32 + 8 halves pad
#define NSTAGE  3

#define CPASYNC(dst, src) \
    asm volatile("cp.async.cg.shared.global [%0], [%1], 16;\n" :: "r"(dst), "l"(src))
#define LDSM4(d, addr) \
    asm volatile("ldmatrix.sync.aligned.m8n8.x4.shared.b16 {%0,%1,%2,%3}, [%4];" \
        : "=r"((d)[0]), "=r"((d)[1]), "=r"((d)[2]), "=r"((d)[3]) : "r"(addr))
#define MMA16816(c, a, b) \
    asm volatile("mma.sync.aligned.m16n8k16.row.col.f32.f16.f16.f32 " \
        "{%0,%1,%2,%3}, {%4,%5,%6,%7}, {%8,%9}, {%0,%1,%2,%3};" \
        : "+f"((c)[0]), "+f"((c)[1]), "+f"((c)[2]), "+f"((c)[3]) \
        : "r"((a)[0]), "r"((a)[1]), "r"((a)[2]), "r"((a)[3]), "r"((b)[0]), "r"((b)[1]))

extern __shared__ __align__(128) unsigned char smem_buf[];

// ---------------- small GEMM: 128x128 tile (hidden + logits, split-K 4) -------
#define TILEH1   (128 * LDT)
#define STAGEH1  (2 * TILEH1)
#define SMEM1    (NSTAGE * STAGEH1 * 2)     // 61440

__global__ __launch_bounds__(256, 2)
void gemm128_kernel(const __half* __restrict__ A, int lda,
                    const __half* __restrict__ B, int ldb,
                    float* __restrict__ C, int ldc, int Kdim)
{
    const int tid = threadIdx.x, lane = tid & 31, warp = tid >> 5;
    const int wm = warp >> 2, wn = warp & 3;
    const int bm = blockIdx.y << 7;
    const uint32_t smbase = smem_u32(smem_buf);

    const int koff = blockIdx.z * Kdim;
    A += koff; B += koff;
    C += (size_t)blockIdx.z * M_TOK * ldc;

    const int r0 = tid >> 2, q0 = (tid & 3) << 3, r1 = r0 + 64;
    const uint32_t ob0 = (uint32_t)(r0 * LDT + q0) * 2;
    const uint32_t ob1 = (uint32_t)(r1 * LDT + q0) * 2;

    const __half* gA0 = A + (size_t)(bm + r0) * lda + q0;
    const __half* gA1 = A + (size_t)(bm + r1) * lda + q0;
    const __half* gB0 = B + (size_t)r0 * ldb + q0;
    const __half* gB1 = B + (size_t)r1 * ldb + q0;

    auto issue_stage = [&](int st, int k0) {
        uint32_t sb = smbase + (uint32_t)st * (STAGEH1 * 2);
        CPASYNC(sb + ob0, gA0 + k0);
        CPASYNC(sb + ob1, gA1 + k0);
        CPASYNC(sb + TILEH1 * 2 + ob0, gB0 + k0);
        CPASYNC(sb + TILEH1 * 2 + ob1, gB1 + k0);
        asm volatile("cp.async.commit_group;\n" ::);
    };

    const uint32_t aBase = (uint32_t)((wm * 64 + (lane & 15)) * LDT + ((lane >> 4) << 3));
    const uint32_t bBase = (uint32_t)((wn * 32 + ((lane >> 4) << 3) + (lane & 7)) * LDT
                                      + (((lane >> 3) & 1) << 3));
    float acc[4][4][4] = {};
    const int nk = Kdim >> 5;

    issue_stage(0, 0);
    if (nk > 1) issue_stage(1, 32);

    for (int kt = 0; kt < nk; kt++) {
        if (kt + 2 < nk) {
            issue_stage((kt + 2) % NSTAGE, (kt + 2) << 5);
            asm volatile("cp.async.wait_group 2;\n" ::: "memory");
        } else if (kt + 1 < nk) {
            asm volatile("cp.async.wait_group 1;\n" ::: "memory");
        } else {
            asm volatile("cp.async.wait_group 0;\n" ::: "memory");
        }
        __syncthreads();

        uint32_t sb = smbase + (uint32_t)(kt % NSTAGE) * (STAGEH1 * 2);
        #pragma unroll
        for (int kk = 0; kk < 32; kk += 16) {
            uint32_t a[4][4], b[4][2];
            #pragma unroll
            for (int mi = 0; mi < 4; mi++)
                LDSM4(a[mi], sb + (aBase + mi * (16 * LDT) + kk) * 2);
            #pragma unroll
            for (int h = 0; h < 2; h++) {
                uint32_t t4[4];
                LDSM4(t4, sb + TILEH1 * 2 + (bBase + h * (16 * LDT) + kk) * 2);
                b[2*h][0] = t4[0]; b[2*h][1] = t4[1];
                b[2*h+1][0] = t4[2]; b[2*h+1][1] = t4[3];
            }
            #pragma unroll
            for (int mi = 0; mi < 4; mi++)
                #pragma unroll
                for (int nj = 0; nj < 4; nj++)
                    MMA16816(acc[mi][nj], a[mi], b[nj]);
        }
        __syncthreads();
    }

    const int tr = lane >> 2, tc2 = (lane & 3) << 1;
    #pragma unroll
    for (int mi = 0; mi < 4; mi++) {
        int row = bm + wm * 64 + mi * 16 + tr;
        #pragma unroll
        for (int nj = 0; nj < 4; nj++) {
            int col = wn * 32 + nj * 8 + tc2;
            *(float2*)(C + (size_t)row * ldc + col) = make_float2(acc[mi][nj][0], acc[mi][nj][1]);
            *(float2*)(C + (size_t)(row + 8) * ldc + col) = make_float2(acc[mi][nj][2], acc[mi][nj][3]);
        }
    }
}

// ---------------- main GEMM: 128x256 block, 64x64 warp tile -------------------
#define ATILEH   (128 * LDT)                // A halves per stage
#define BTILEH   (256 * LDT)                // B halves per stage
#define ABYTES   (ATILEH * 2)               // 10240
#define STAGE2   ((ATILEH + BTILEH) * 2)    // 30720 B
#define SMEM2    (NSTAGE * STAGE2)          // 92160 B

__global__ __launch_bounds__(256, 1)
void gemm_main_kernel(const __half* __restrict__ A,
                      const __half* __restrict__ B,
                      float* __restrict__ C,
                      const float* __restrict__ bias)
{
    const int tid = threadIdx.x, lane = tid & 31, warp = tid >> 5;
    const int wm = warp >> 2, wn = warp & 3;            // 2 x 4 warps, tile 64x64
    const int bm = blockIdx.y << 7, bn = blockIdx.x << 8;
    const uint32_t smbase = smem_u32(smem_buf);

    // cp.async mapping: A 512 chunks (2/thread), B 1024 chunks (4/thread)
    const int ar0 = tid >> 2, aq = (tid & 3) << 3, ar1 = ar0 + 64;
    const uint32_t aob0 = (uint32_t)(ar0 * LDT + aq) * 2;
    const uint32_t aob1 = (uint32_t)(ar1 * LDT + aq) * 2;
    const __half* gA0 = A + (size_t)(bm + ar0) * KTOT + aq;
    const __half* gA1 = A + (size_t)(bm + ar1) * KTOT + aq;

    const __half* gB[4];
    uint32_t bob[4];
    #pragma unroll
    for (int j = 0; j < 4; j++) {
        int c = tid + 256 * j;
        int br = c >> 2, bq = (c & 3) << 3;
        bob[j] = (uint32_t)(br * LDT + bq) * 2;
        gB[j] = B + (size_t)(bn + br) * KTOT + bq;
    }

    auto issue_stage = [&](int st, int k0) {
        uint32_t sb = smbase + (uint32_t)st * STAGE2;
        CPASYNC(sb + aob0, gA0 + k0);
        CPASYNC(sb + aob1, gA1 + k0);
        uint32_t bb = sb + ABYTES;
        #pragma unroll
        for (int j = 0; j < 4; j++) CPASYNC(bb + bob[j], gB[j] + k0);
        asm volatile("cp.async.commit_group;\n" ::);
    };

    const uint32_t aBase = (uint32_t)((wm * 64 + (lane & 15)) * LDT + ((lane >> 4) << 3));
    const uint32_t bBase = (uint32_t)((wn * 64 + ((lane >> 4) << 3) + (lane & 7)) * LDT
                                      + (((lane >> 3) & 1) << 3));
    float acc[4][8][4] = {};
    const int nk = KTOT >> 5;                           // 160

    issue_stage(0, 0);
    issue_stage(1, 32);

    for (int kt = 0; kt < nk; kt++) {
        if (kt + 2 < nk) {
            issue_stage((kt + 2) % NSTAGE, (kt + 2) << 5);
            asm volatile("cp.async.wait_group 2;\n" ::: "memory");
        } else if (kt + 1 < nk) {
            asm volatile("cp.async.wait_group 1;\n" ::: "memory");
        } else {
            asm volatile("cp.async.wait_group 0;\n" ::: "memory");
        }
        __syncthreads();

        uint32_t sb = smbase + (uint32_t)(kt % NSTAGE) * STAGE2;
        #pragma unroll
        for (int kk = 0; kk < 32; kk += 16) {
            uint32_t a[4][4], b[8][2];
            #pragma unroll
            for (int mi = 0; mi < 4; mi++)
                LDSM4(a[mi], sb + (aBase + mi * (16 * LDT) + kk) * 2);
            #pragma unroll
            for (int h = 0; h < 4; h++) {
                uint32_t t4[4];
                LDSM4(t4, sb + ABYTES + (bBase + h * (16 * LDT) + kk) * 2);
                b[2*h][0] = t4[0]; b[2*h][1] = t4[1];
                b[2*h+1][0] = t4[2]; b[2*h+1][1] = t4[3];
            }
            #pragma unroll
            for (int mi = 0; mi < 4; mi++)
                #pragma unroll
                for (int nj = 0; nj < 8; nj++)
                    MMA16816(acc[mi][nj], a[mi], b[nj]);
        }
        __syncthreads();
    }

    // epilogue
    const int tr = lane >> 2, tc2 = (lane & 3) << 1;
    #pragma unroll
    for (int mi = 0; mi < 4; mi++) {
        int row = bm + wm * 64 + mi * 16 + tr;
        #pragma unroll
        for (int nj = 0; nj < 8; nj++) {
            int col = bn + wn * 64 + nj * 8 + tc2;
            float b0 = bias[col], b1 = bias[col + 1];
            *(float2*)(C + (size_t)row * DOUT + col) =
                make_float2(acc[mi][nj][0] + b0, acc[mi][nj][1] + b1);
            *(float2*)(C + (size_t)(row + 8) * DOUT + col) =
                make_float2(acc[mi][nj][2] + b0, acc[mi][nj][3] + b1);
        }
    }
}

// ---------------- launch ------------------------------------------------------
extern "C" void kernel_launch(void* const* d_in, const int* in_sizes, int n_in,
                              void* d_out, int out_size)
{
    const float* x  = (const float*)d_in[0];
    const float* bw = (const float*)d_in[1];
    const float* bb = (const float*)d_in[2];
    const float* Am = (const float*)d_in[3];
    const float* Bm = (const float*)d_in[4];
    const float* rw = (const float*)d_in[5];
    float* out = (float*)d_out;

    void *pxg, *pwt, *pw2, *phl;
    cudaGetSymbolAddress(&pxg, g_xg);
    cudaGetSymbolAddress(&pwt, g_wt);
    cudaGetSymbolAddress(&pw2, g_w2);
    cudaGetSymbolAddress(&phl, g_hl);

    cudaFuncSetAttribute(gemm128_kernel,
                         cudaFuncAttributeMaxDynamicSharedMemorySize, SMEM1);
    cudaFuncSetAttribute(gemm_main_kernel,
                         cudaFuncAttributeMaxDynamicSharedMemorySize, SMEM2);

    convert_x_kernel<<<(M_TOK * DIN / 4) / 256, 256>>>((const float4*)x);
    prep_w_kernel<<<(DOUT * KTOT / 4) / 256, 256>>>(bw, Bm);
    prep_w2_kernel<<<(128 * DIN / 4) / 256, 256>>>(Am, rw);

    // hidden + router logits: [8192,128] = x @ w2^T, split-K 4
    gemm128_kernel<<<dim3(1, 64, 4), 256, SMEM1>>>(
        (const __half*)pxg, KTOT,
        (const __half*)pw2, DIN,
        (float*)phl, 128, DIN / 4);

    router_kernel<<<M_TOK / 8, 256>>>();

    // main fused GEMM: out = [x|g] @ [base_w|B_flat]^T + bias
    gemm_main_kernel<<<dim3(DOUT / 256, M_TOK / 128), 256, SMEM2>>>(
        (const __half*)pxg, (const __half*)pwt, out, bb);
}

// round 11
// speedup vs baseline: 1.2347x; 1.2347x over previous
#include <cuda_runtime.h>
#include <cuda_fp16.h>
#include <cstdint>

#define M_TOK   8192
#define DIN     4096
#define DOUT    4096
#define RNK     64
#define NEXP    16
#define KG      1024
#define KTOT    5120
#define SCALING 0.5f

// ---------------- scratch (static device globals; no allocations) -----------
__device__ __half g_xg[(size_t)M_TOK * KTOT];   // 80 MB  [x | g] fp16, row-major
__device__ __half g_wt[(size_t)DOUT * KTOT];    // 40 MB  [base_w | B_flat] fp16
__device__ __half g_w2[128 * DIN];              //  1 MB  [A; router_w; 0] fp16
__device__ float  g_hl[4 * M_TOK * 128];        // 16 MB  split-K partials (4 planes)

// ---------------- helpers ----------------------------------------------------
__device__ __forceinline__ uint32_t smem_u32(const void* p) {
    return (uint32_t)__cvta_generic_to_shared(p);
}
__device__ __forceinline__ uint32_t pack2h(__half a, __half b) {
    return (uint32_t)__half_as_ushort(a) | ((uint32_t)__half_as_ushort(b) << 16);
}

// ---------------- conversion kernels -----------------------------------------
__global__ void convert_x_kernel(const float4* __restrict__ x4) {
    int i = blockIdx.x * blockDim.x + threadIdx.x;      // < M_TOK*DIN/4
    float4 v = x4[i];
    int e = i << 2;
    int row = e >> 12, col = e & (DIN - 1);
    *(uint2*)(g_xg + (size_t)row * KTOT + col) =
        make_uint2(pack2h(__float2half_rn(v.x), __float2half_rn(v.y)),
                   pack2h(__float2half_rn(v.z), __float2half_rn(v.w)));
}

__global__ void prep_w_kernel(const float* __restrict__ bw, const float* __restrict__ Bm) {
    int i = blockIdx.x * blockDim.x + threadIdx.x;      // < DOUT*KTOT/4
    int e = i << 2;
    int o = e / KTOT, k = e - o * KTOT;
    float4 v;
    if (k < DIN) {
        v = *(const float4*)(bw + (size_t)o * DIN + k);
    } else {
        int kk = k - DIN, ei = kk >> 6, r = kk & 63;
        v = *(const float4*)(Bm + ((size_t)(ei * DOUT + o) * RNK + r));
    }
    *(uint2*)(g_wt + (size_t)o * KTOT + k) =
        make_uint2(pack2h(__float2half_rn(v.x), __float2half_rn(v.y)),
                   pack2h(__float2half_rn(v.z), __float2half_rn(v.w)));
}

__global__ void prep_w2_kernel(const float* __restrict__ Am, const float* __restrict__ rw) {
    int i = blockIdx.x * blockDim.x + threadIdx.x;      // < 128*DIN/4
    int e = i << 2;
    int r = e >> 12, k = e & (DIN - 1);
    float4 v = make_float4(0.f, 0.f, 0.f, 0.f);
    if (r < 64)      v = *(const float4*)(Am + (size_t)r * DIN + k);
    else if (r < 80) v = *(const float4*)(rw + (size_t)(r - 64) * DIN + k);
    *(uint2*)(g_w2 + (size_t)r * DIN + k) =
        make_uint2(pack2h(__float2half_rn(v.x), __float2half_rn(v.y)),
                   pack2h(__float2half_rn(v.z), __float2half_rn(v.w)));
}

// ---------------- router: softmax/top2 -> g columns of g_xg -------------------
__global__ void router_kernel() {
    int warp = threadIdx.x >> 5, lane = threadIdx.x & 31;
    int t = blockIdx.x * 8 + warp;
    __shared__ float wsel[8][16];
    const float* p0 = g_hl + (size_t)t * 128;
    const float* p1 = p0 + (size_t)M_TOK * 128;
    const float* p2 = p1 + (size_t)M_TOK * 128;
    const float* p3 = p2 + (size_t)M_TOK * 128;
    if (lane == 0) {
        float lg[16]; float m = -1e30f;
        #pragma unroll
        for (int e = 0; e < 16; e++) {
            lg[e] = p0[64 + e] + p1[64 + e] + p2[64 + e] + p3[64 + e];
            m = fmaxf(m, lg[e]);
        }
        float p[16], Z = 0.f;
        #pragma unroll
        for (int e = 0; e < 16; e++) { p[e] = expf(lg[e] - m); Z += p[e]; }
        float inv = 1.f / Z;
        int i1 = 0; float b1 = -1.f;
        #pragma unroll
        for (int e = 0; e < 16; e++) if (p[e] > b1) { b1 = p[e]; i1 = e; }
        int i2 = 0; float b2 = -1.f;
        #pragma unroll
        for (int e = 0; e < 16; e++) if (e != i1 && p[e] > b2) { b2 = p[e]; i2 = e; }
        b1 *= inv; b2 *= inv;
        float den = b1 + b2 + 1e-6f;
        #pragma unroll
        for (int e = 0; e < 16; e++) wsel[warp][e] = 0.f;
        wsel[warp][i1] = (b1 / den) * SCALING;
        wsel[warp][i2] = (b2 / den) * SCALING;
    }
    __syncwarp();
    __half* grow = g_xg + (size_t)t * KTOT + DIN;
    for (int c = lane; c < KG; c += 32) {
        float v = wsel[warp][c >> 6] * (p0[c & 63] + p1[c & 63] + p2[c & 63] + p3[c & 63]);
        grow[c] = __float2half_rn(v);
    }
}

// ---------------- common GEMM macros ------------------------------------------
#define CPASYNC(dst, src) \
    asm volatile("cp.async.cg.shared.global [%0], [%1], 16;\n" :: "r"(dst), "l"(src))
#define LDSM4(d, addr) \
    asm volatile("ldmatrix.sync.aligned.m8n8.x4.shared.b16 {%0,%1,%2,%3}, [%4];" \
        : "=r"((d)[0]), "=r"((d)[1]), "=r"((d)[2]), "=r"((d)[3]) : "r"(addr))
#define MMA16816(c, a, b) \
    asm volatile("mma.sync.aligned.m16n8k16.row.col.f32.f16.f16.f32 " \
        "{%0,%1,%2,%3}, {%4,%5,%6,%7}, {%8,%9}, {%0,%1,%2,%3};" \
        : "+f"((c)[0]), "+f"((c)[1]), "+f"((c)[2]), "+f"((c)[3]) \
        : "r"((a)[0]), "r"((a)[1]), "r"((a)[2]), "r"((a)[3]), "r"((b)[0]), "r"((b)[1]))

extern __shared__ __align__(128) unsigned char smem_buf[];

// ---------------- small GEMM: 128x128 tile, K32 chunks (split-K 4) ------------
#define LDT1     40
#define TILEH1   (128 * LDT1)
#define STAGEH1  (2 * TILEH1)
#define SMEM1    (3 * STAGEH1 * 2)          // 61440

__global__ __launch_bounds__(256, 2)
void gemm128_kernel(const __half* __restrict__ A, int lda,
                    const __half* __restrict__ B, int ldb,
                    float* __restrict__ C, int ldc, int Kdim)
{
    const int tid = threadIdx.x, lane = tid & 31, warp = tid >> 5;
    const int wm = warp >> 2, wn = warp & 3;
    const int bm = blockIdx.y << 7;
    const uint32_t smbase = smem_u32(smem_buf);

    const int koff = blockIdx.z * Kdim;
    A += koff; B += koff;
    C += (size_t)blockIdx.z * M_TOK * ldc;

    const int r0 = tid >> 2, q0 = (tid & 3) << 3, r1 = r0 + 64;
    const uint32_t ob0 = (uint32_t)(r0 * LDT1 + q0) * 2;
    const uint32_t ob1 = (uint32_t)(r1 * LDT1 + q0) * 2;

    const __half* gA0 = A + (size_t)(bm + r0) * lda + q0;
    const __half* gA1 = A + (size_t)(bm + r1) * lda + q0;
    const __half* gB0 = B + (size_t)r0 * ldb + q0;
    const __half* gB1 = B + (size_t)r1 * ldb + q0;

    auto issue_stage = [&](int st, int k0) {
        uint32_t sb = smbase + (uint32_t)st * (STAGEH1 * 2);
        CPASYNC(sb + ob0, gA0 + k0);
        CPASYNC(sb + ob1, gA1 + k0);
        CPASYNC(sb + TILEH1 * 2 + ob0, gB0 + k0);
        CPASYNC(sb + TILEH1 * 2 + ob1, gB1 + k0);
        asm volatile("cp.async.commit_group;\n" ::);
    };

    const uint32_t aBase = (uint32_t)((wm * 64 + (lane & 15)) * LDT1 + ((lane >> 4) << 3));
    const uint32_t bBase = (uint32_t)((wn * 32 + ((lane >> 4) << 3) + (lane & 7)) * LDT1
                                      + (((lane >> 3) & 1) << 3));
    float acc[4][4][4] = {};
    const int nk = Kdim >> 5;

    issue_stage(0, 0);
    if (nk > 1) issue_stage(1, 32);

    for (int kt = 0; kt < nk; kt++) {
        if (kt + 2 < nk) {
            issue_stage((kt + 2) % 3, (kt + 2) << 5);
            asm volatile("cp.async.wait_group 2;\n" ::: "memory");
        } else if (kt + 1 < nk) {
            asm volatile("cp.async.wait_group 1;\n" ::: "memory");
        } else {
            asm volatile("cp.async.wait_group 0;\n" ::: "memory");
        }
        __syncthreads();

        uint32_t sb = smbase + (uint32_t)(kt % 3) * (STAGEH1 * 2);
        #pragma unroll
        for (int kk = 0; kk < 32; kk += 16) {
            uint32_t a[4][4], b[4][2];
            #pragma unroll
            for (int mi = 0; mi < 4; mi++)
                LDSM4(a[mi], sb + (aBase + mi * (16 * LDT1) + kk) * 2);
            #pragma unroll
            for (int h = 0; h < 2; h++) {
                uint32_t t4[4];
                LDSM4(t4, sb + TILEH1 * 2 + (bBase + h * (16 * LDT1) + kk) * 2);
                b[2*h][0] = t4[0]; b[2*h][1] = t4[1];
                b[2*h+1][0] = t4[2]; b[2*h+1][1] = t4[3];
            }
            #pragma unroll
            for (int mi = 0; mi < 4; mi++)
                #pragma unroll
                for (int nj = 0; nj < 4; nj++)
                    MMA16816(acc[mi][nj], a[mi], b[nj]);
        }
        __syncthreads();
    }

    const int tr = lane >> 2, tc2 = (lane & 3) << 1;
    #pragma unroll
    for (int mi = 0; mi < 4; mi++) {
        int row = bm + wm * 64 + mi * 16 + tr;
        #pragma unroll
        for (int nj = 0; nj < 4; nj++) {
            int col = wn * 32 + nj * 8 + tc2;
            *(float2*)(C + (size_t)row * ldc + col) = make_float2(acc[mi][nj][0], acc[mi][nj][1]);
            *(float2*)(C + (size_t)(row + 8) * ldc + col) = make_float2(acc[mi][nj][2], acc[mi][nj][3]);
        }
    }
}

// ---------------- main GEMM: 128x128 block, 64x32 warp tile, K64 chunks -------
#define LDT2     72                         // 64 + 8 halves pad (144B rows)
#define TILEH2   (128 * LDT2)               // halves per tile (A or B)
#define STAGE2B  (2 * TILEH2 * 2)           // 36864 B per stage
#define SMEM2    (3 * STAGE2B)              // 110592 B (2 CTAs/SM = 221KB)

__global__ __launch_bounds__(256, 2)
void gemm_main_kernel(const __half* __restrict__ A,
                      const __half* __restrict__ B,
                      float* __restrict__ C,
                      const float* __restrict__ bias)
{
    const int tid = threadIdx.x, lane = tid & 31, warp = tid >> 5;
    const int wm = warp >> 2, wn = warp & 3;            // 2 x 4 warps, tile 64x32
    const int bm = blockIdx.y << 7, bn = blockIdx.x << 7;
    const uint32_t smbase = smem_u32(smem_buf);

    // cp.async: per stage, A and B are each 128 rows x 128B = 1024 chunks; 4/thread
    uint32_t aob[4], bob[4];
    const __half *gA[4], *gB[4];
    #pragma unroll
    for (int j = 0; j < 4; j++) {
        int c = tid + 256 * j;
        int row = c >> 3, q = (c & 7) << 3;
        aob[j] = (uint32_t)(row * LDT2 + q) * 2;
        bob[j] = aob[j];
        gA[j] = A + (size_t)(bm + row) * KTOT + q;
        gB[j] = B + (size_t)(bn + row) * KTOT + q;
    }

    auto issue_stage = [&](int st, int k0) {
        uint32_t sb = smbase + (uint32_t)st * STAGE2B;
        #pragma unroll
        for (int j = 0; j < 4; j++) CPASYNC(sb + aob[j], gA[j] + k0);
        uint32_t sb2 = sb + TILEH2 * 2;
        #pragma unroll
        for (int j = 0; j < 4; j++) CPASYNC(sb2 + bob[j], gB[j] + k0);
        asm volatile("cp.async.commit_group;\n" ::);
    };

    const uint32_t aBase = (uint32_t)((wm * 64 + (lane & 15)) * LDT2 + ((lane >> 4) << 3));
    const uint32_t bBase = (uint32_t)((wn * 32 + ((lane >> 4) << 3) + (lane & 7)) * LDT2
                                      + (((lane >> 3) & 1) << 3));
    float acc[4][4][4] = {};
    const int nk = KTOT >> 6;                           // 80

    issue_stage(0, 0);
    issue_stage(1, 64);

    for (int kt = 0; kt < nk; kt++) {
        if (kt + 2 < nk) {
            issue_stage((kt + 2) % 3, (kt + 2) << 6);
            asm volatile("cp.async.wait_group 2;\n" ::: "memory");
        } else if (kt + 1 < nk) {
            asm volatile("cp.async.wait_group 1;\n" ::: "memory");
        } else {
            asm volatile("cp.async.wait_group 0;\n" ::: "memory");
        }
        __syncthreads();

        uint32_t sb = smbase + (uint32_t)(kt % 3) * STAGE2B;
        #pragma unroll
        for (int kk = 0; kk < 64; kk += 16) {
            uint32_t a[4][4], b[4][2];
            #pragma unroll
            for (int mi = 0; mi < 4; mi++)
                LDSM4(a[mi], sb + (aBase + mi * (16 * LDT2) + kk) * 2);
            #pragma unroll
            for (int h = 0; h < 2; h++) {
                uint32_t t4[4];
                LDSM4(t4, sb + TILEH2 * 2 + (bBase + h * (16 * LDT2) + kk) * 2);
                b[2*h][0] = t4[0]; b[2*h][1] = t4[1];
                b[2*h+1][0] = t4[2]; b[2*h+1][1] = t4[3];
            }
            #pragma unroll
            for (int mi = 0; mi < 4; mi++)
                #pragma unroll
                for (int nj = 0; nj < 4; nj++)
                    MMA16816(acc[mi][nj], a[mi], b[nj]);
        }
        __syncthreads();
    }

    // epilogue
    const int tr = lane >> 2, tc2 = (lane & 3) << 1;
    #pragma unroll
    for (int mi = 0; mi < 4; mi++) {
        int row = bm + wm * 64 + mi * 16 + tr;
        #pragma unroll
        for (int nj = 0; nj < 4; nj++) {
            int col = bn + wn * 32 + nj * 8 + tc2;
            float b0 = bias[col], b1 = bias[col + 1];
            *(float2*)(C + (size_t)row * DOUT + col) =
                make_float2(acc[mi][nj][0] + b0, acc[mi][nj][1] + b1);
            *(float2*)(C + (size_t)(row + 8) * DOUT + col) =
                make_float2(acc[mi][nj][2] + b0, acc[mi][nj][3] + b1);
        }
    }
}

// ---------------- launch ------------------------------------------------------
extern "C" void kernel_launch(void* const* d_in, const int* in_sizes, int n_in,
                              void* d_out, int out_size)
{
    const float* x  = (const float*)d_in[0];
    const float* bw = (const float*)d_in[1];
    const float* bb = (const float*)d_in[2];
    const float* Am = (const float*)d_in[3];
    const float* Bm = (const float*)d_in[4];
    const float* rw = (const float*)d_in[5];
    float* out = (float*)d_out;

    void *pxg, *pwt, *pw2, *phl;
    cudaGetSymbolAddress(&pxg, g_xg);
    cudaGetSymbolAddress(&pwt, g_wt);
    cudaGetSymbolAddress(&pw2, g_w2);
    cudaGetSymbolAddress(&phl, g_hl);

    cudaFuncSetAttribute(gemm128_kernel,
                         cudaFuncAttributeMaxDynamicSharedMemorySize, SMEM1);
    cudaFuncSetAttribute(gemm_main_kernel,
                         cudaFuncAttributeMaxDynamicSharedMemorySize, SMEM2);

    convert_x_kernel<<<(M_TOK * DIN / 4) / 256, 256>>>((const float4*)x);
    prep_w_kernel<<<(DOUT * KTOT / 4) / 256, 256>>>(bw, Bm);
    prep_w2_kernel<<<(128 * DIN / 4) / 256, 256>>>(Am, rw);

    // hidden + router logits: [8192,128] = x @ w2^T, split-K 4
    gemm128_kernel<<<dim3(1, 64, 4), 256, SMEM1>>>(
        (const __half*)pxg, KTOT,
        (const __half*)pw2, DIN,
        (float*)phl, 128, DIN / 4);

    router_kernel<<<M_TOK / 8, 256>>>();

    // main fused GEMM: out = [x|g] @ [base_w|B_flat]^T + bias
    gemm_main_kernel<<<dim3(DOUT / 128, M_TOK / 128), 256, SMEM2>>>(
        (const __half*)pxg, (const __half*)pwt, out, bb);
}

// round 12
// speedup vs baseline: 1.2397x; 1.0040x over previous
#include <cuda_runtime.h>
#include <cuda_fp16.h>
#include <cstdint>

#define M_TOK   8192
#define DIN     4096
#define DOUT    4096
#define RNK     64
#define NEXP    16
#define KG      1024
#define KTOT    5120
#define SCALING 0.5f
#define NSPLIT  8

// ---------------- scratch (static device globals; no allocations) -----------
__device__ __half g_xg[(size_t)M_TOK * KTOT];   // 80 MB  [x | g] fp16, row-major
__device__ __half g_wt[(size_t)DOUT * KTOT];    // 40 MB  [base_w | B_flat] fp16
__device__ __half g_w2[128 * DIN];              //  1 MB  [A; router_w; 0] fp16
__device__ float  g_hl[NSPLIT * M_TOK * 128];   // 32 MB  split-K partials (8 planes)

// ---------------- helpers ----------------------------------------------------
__device__ __forceinline__ uint32_t smem_u32(const void* p) {
    return (uint32_t)__cvta_generic_to_shared(p);
}
__device__ __forceinline__ uint32_t pack2h(__half a, __half b) {
    return (uint32_t)__half_as_ushort(a) | ((uint32_t)__half_as_ushort(b) << 16);
}
__device__ __forceinline__ uint2 cvt4(float4 v) {
    return make_uint2(pack2h(__float2half_rn(v.x), __float2half_rn(v.y)),
                      pack2h(__float2half_rn(v.z), __float2half_rn(v.w)));
}

// ---------------- merged conversion kernel ------------------------------------
#define NX   (M_TOK * DIN / 4)              // 8388608  x items
#define NW   (DOUT * KTOT / 4)              // 5242880  W items
#define NW2  (128 * DIN / 4)                // 131072   w2 items
#define NPREP (NX + NW + NW2)               // 13762560 = 53760 * 256

__global__ void prep_all_kernel(const float4* __restrict__ x4,
                                const float* __restrict__ bw,
                                const float* __restrict__ Bm,
                                const float* __restrict__ Am,
                                const float* __restrict__ rw)
{
    int i = blockIdx.x * blockDim.x + threadIdx.x;
    if (i < NX) {
        float4 v = x4[i];
        int e = i << 2;
        int row = e >> 12, col = e & (DIN - 1);
        *(uint2*)(g_xg + (size_t)row * KTOT + col) = cvt4(v);
    } else if (i < NX + NW) {
        int j = i - NX;
        int e = j << 2;
        int o = e / KTOT, k = e - o * KTOT;
        float4 v;
        if (k < DIN) {
            v = *(const float4*)(bw + (size_t)o * DIN + k);
        } else {
            int kk = k - DIN, ei = kk >> 6, r = kk & 63;
            v = *(const float4*)(Bm + ((size_t)(ei * DOUT + o) * RNK + r));
        }
        *(uint2*)(g_wt + (size_t)o * KTOT + k) = cvt4(v);
    } else {
        int j = i - NX - NW;
        int e = j << 2;
        int r = e >> 12, k = e & (DIN - 1);
        float4 v = make_float4(0.f, 0.f, 0.f, 0.f);
        if (r < 64)      v = *(const float4*)(Am + (size_t)r * DIN + k);
        else if (r < 80) v = *(const float4*)(rw + (size_t)(r - 64) * DIN + k);
        *(uint2*)(g_w2 + (size_t)r * DIN + k) = cvt4(v);
    }
}

// ---------------- router: softmax/top2 -> g columns of g_xg -------------------
__global__ void router_kernel() {
    int warp = threadIdx.x >> 5, lane = threadIdx.x & 31;
    int t = blockIdx.x * 8 + warp;
    __shared__ float wsel[8][16];
    __shared__ float hsum[8][64];
    const float* p0 = g_hl + (size_t)t * 128;

    // parallel reduce of 8 split-K planes: lanes 0..15 handle logits, all handle h
    if (lane < 16) {
        float lg = 0.f;
        #pragma unroll
        for (int s = 0; s < NSPLIT; s++) lg += p0[(size_t)s * M_TOK * 128 + 64 + lane];
        wsel[warp][lane] = lg;                     // temp: raw logits
    }
    #pragma unroll
    for (int c = lane; c < 64; c += 32) {
        float hv = 0.f;
        #pragma unroll
        for (int s = 0; s < NSPLIT; s++) hv += p0[(size_t)s * M_TOK * 128 + c];
        hsum[warp][c] = hv;
    }
    __syncwarp();
    if (lane == 0) {
        float lg[16]; float m = -1e30f;
        #pragma unroll
        for (int e = 0; e < 16; e++) { lg[e] = wsel[warp][e]; m = fmaxf(m, lg[e]); }
        float p[16], Z = 0.f;
        #pragma unroll
        for (int e = 0; e < 16; e++) { p[e] = expf(lg[e] - m); Z += p[e]; }
        float inv = 1.f / Z;
        int i1 = 0; float b1 = -1.f;
        #pragma unroll
        for (int e = 0; e < 16; e++) if (p[e] > b1) { b1 = p[e]; i1 = e; }
        int i2 = 0; float b2 = -1.f;
        #pragma unroll
        for (int e = 0; e < 16; e++) if (e != i1 && p[e] > b2) { b2 = p[e]; i2 = e; }
        b1 *= inv; b2 *= inv;
        float den = b1 + b2 + 1e-6f;
        #pragma unroll
        for (int e = 0; e < 16; e++) wsel[warp][e] = 0.f;
        wsel[warp][i1] = (b1 / den) * SCALING;
        wsel[warp][i2] = (b2 / den) * SCALING;
    }
    __syncwarp();
    __half* grow = g_xg + (size_t)t * KTOT + DIN;
    #pragma unroll
    for (int c = lane; c < KG; c += 32) {
        grow[c] = __float2half_rn(wsel[warp][c >> 6] * hsum[warp][c & 63]);
    }
}

// ---------------- common GEMM macros ------------------------------------------
#define CPASYNC(dst, src) \
    asm volatile("cp.async.cg.shared.global [%0], [%1], 16;\n" :: "r"(dst), "l"(src))
#define LDSM4(d, addr) \
    asm volatile("ldmatrix.sync.aligned.m8n8.x4.shared.b16 {%0,%1,%2,%3}, [%4];" \
        : "=r"((d)[0]), "=r"((d)[1]), "=r"((d)[2]), "=r"((d)[3]) : "r"(addr))
#define MMA16816(c, a, b) \
    asm volatile("mma.sync.aligned.m16n8k16.row.col.f32.f16.f16.f32 " \
        "{%0,%1,%2,%3}, {%4,%5,%6,%7}, {%8,%9}, {%0,%1,%2,%3};" \
        : "+f"((c)[0]), "+f"((c)[1]), "+f"((c)[2]), "+f"((c)[3]) \
        : "r"((a)[0]), "r"((a)[1]), "r"((a)[2]), "r"((a)[3]), "r"((b)[0]), "r"((b)[1]))

extern __shared__ __align__(128) unsigned char smem_buf[];

// ---------------- small GEMM: 128x128 tile, K32 chunks (split-K 8) ------------
#define LDT1     40
#define TILEH1   (128 * LDT1)
#define STAGEH1  (2 * TILEH1)
#define SMEM1    (3 * STAGEH1 * 2)          // 61440

__global__ __launch_bounds__(256, 2)
void gemm128_kernel(const __half* __restrict__ A, int lda,
                    const __half* __restrict__ B, int ldb,
                    float* __restrict__ C, int ldc, int Kdim)
{
    const int tid = threadIdx.x, lane = tid & 31, warp = tid >> 5;
    const int wm = warp >> 2, wn = warp & 3;
    const int bm = blockIdx.y << 7;
    const uint32_t smbase = smem_u32(smem_buf);

    const int koff = blockIdx.z * Kdim;
    A += koff; B += koff;
    C += (size_t)blockIdx.z * M_TOK * ldc;

    const int r0 = tid >> 2, q0 = (tid & 3) << 3, r1 = r0 + 64;
    const uint32_t ob0 = (uint32_t)(r0 * LDT1 + q0) * 2;
    const uint32_t ob1 = (uint32_t)(r1 * LDT1 + q0) * 2;

    const __half* gA0 = A + (size_t)(bm + r0) * lda + q0;
    const __half* gA1 = A + (size_t)(bm + r1) * lda + q0;
    const __half* gB0 = B + (size_t)r0 * ldb + q0;
    const __half* gB1 = B + (size_t)r1 * ldb + q0;

    auto issue_stage = [&](int st, int k0) {
        uint32_t sb = smbase + (uint32_t)st * (STAGEH1 * 2);
        CPASYNC(sb + ob0, gA0 + k0);
        CPASYNC(sb + ob1, gA1 + k0);
        CPASYNC(sb + TILEH1 * 2 + ob0, gB0 + k0);
        CPASYNC(sb + TILEH1 * 2 + ob1, gB1 + k0);
        asm volatile("cp.async.commit_group;\n" ::);
    };

    const uint32_t aBase = (uint32_t)((wm * 64 + (lane & 15)) * LDT1 + ((lane >> 4) << 3));
    const uint32_t bBase = (uint32_t)((wn * 32 + ((lane >> 4) << 3) + (lane & 7)) * LDT1
                                      + (((lane >> 3) & 1) << 3));
    float acc[4][4][4] = {};
    const int nk = Kdim >> 5;

    issue_stage(0, 0);
    if (nk > 1) issue_stage(1, 32);

    for (int kt = 0; kt < nk; kt++) {
        if (kt + 2 < nk) {
            issue_stage((kt + 2) % 3, (kt + 2) << 5);
            asm volatile("cp.async.wait_group 2;\n" ::: "memory");
        } else if (kt + 1 < nk) {
            asm volatile("cp.async.wait_group 1;\n" ::: "memory");
        } else {
            asm volatile("cp.async.wait_group 0;\n" ::: "memory");
        }
        __syncthreads();

        uint32_t sb = smbase + (uint32_t)(kt % 3) * (STAGEH1 * 2);
        #pragma unroll
        for (int kk = 0; kk < 32; kk += 16) {
            uint32_t a[4][4], b[4][2];
            #pragma unroll
            for (int mi = 0; mi < 4; mi++)
                LDSM4(a[mi], sb + (aBase + mi * (16 * LDT1) + kk) * 2);
            #pragma unroll
            for (int h = 0; h < 2; h++) {
                uint32_t t4[4];
                LDSM4(t4, sb + TILEH1 * 2 + (bBase + h * (16 * LDT1) + kk) * 2);
                b[2*h][0] = t4[0]; b[2*h][1] = t4[1];
                b[2*h+1][0] = t4[2]; b[2*h+1][1] = t4[3];
            }
            #pragma unroll
            for (int mi = 0; mi < 4; mi++)
                #pragma unroll
                for (int nj = 0; nj < 4; nj++)
                    MMA16816(acc[mi][nj], a[mi], b[nj]);
        }
        __syncthreads();
    }

    const int tr = lane >> 2, tc2 = (lane & 3) << 1;
    #pragma unroll
    for (int mi = 0; mi < 4; mi++) {
        int row = bm + wm * 64 + mi * 16 + tr;
        #pragma unroll
        for (int nj = 0; nj < 4; nj++) {
            int col = wn * 32 + nj * 8 + tc2;
            *(float2*)(C + (size_t)row * ldc + col) = make_float2(acc[mi][nj][0], acc[mi][nj][1]);
            *(float2*)(C + (size_t)(row + 8) * ldc + col) = make_float2(acc[mi][nj][2], acc[mi][nj][3]);
        }
    }
}

// ---------------- main GEMM: 128x128 block, 64x32 warp tile, K64 chunks -------
#define LDT2     72                         // 64 + 8 halves pad (144B rows)
#define TILEH2   (128 * LDT2)               // halves per tile (A or B)
#define STAGE2B  (2 * TILEH2 * 2)           // 36864 B per stage
#define SMEM2    (3 * STAGE2B)              // 110592 B (2 CTAs/SM = 221KB)

__global__ __launch_bounds__(256, 2)
void gemm_main_kernel(const __half* __restrict__ A,
                      const __half* __restrict__ B,
                      float* __restrict__ C,
                      const float* __restrict__ bias)
{
    const int tid = threadIdx.x, lane = tid & 31, warp = tid >> 5;
    const int wm = warp >> 2, wn = warp & 3;            // 2 x 4 warps, tile 64x32
    const int bm = blockIdx.y << 7, bn = blockIdx.x << 7;
    const uint32_t smbase = smem_u32(smem_buf);

    // cp.async: per stage, A and B are each 128 rows x 128B = 1024 chunks; 4/thread
    uint32_t aob[4];
    const __half *gA[4], *gB[4];
    #pragma unroll
    for (int j = 0; j < 4; j++) {
        int c = tid + 256 * j;
        int row = c >> 3, q = (c & 7) << 3;
        aob[j] = (uint32_t)(row * LDT2 + q) * 2;
        gA[j] = A + (size_t)(bm + row) * KTOT + q;
        gB[j] = B + (size_t)(bn + row) * KTOT + q;
    }

    auto issue_stage = [&](int st, int k0) {
        uint32_t sb = smbase + (uint32_t)st * STAGE2B;
        #pragma unroll
        for (int j = 0; j < 4; j++) CPASYNC(sb + aob[j], gA[j] + k0);
        uint32_t sb2 = sb + TILEH2 * 2;
        #pragma unroll
        for (int j = 0; j < 4; j++) CPASYNC(sb2 + aob[j], gB[j] + k0);
        asm volatile("cp.async.commit_group;\n" ::);
    };

    const uint32_t aBase = (uint32_t)((wm * 64 + (lane & 15)) * LDT2 + ((lane >> 4) << 3));
    const uint32_t bBase = (uint32_t)((wn * 32 + ((lane >> 4) << 3) + (lane & 7)) * LDT2
                                      + (((lane >> 3) & 1) << 3));
    float acc[4][4][4] = {};
    const int nk = KTOT >> 6;                           // 80

    issue_stage(0, 0);
    issue_stage(1, 64);

    for (int kt = 0; kt < nk; kt++) {
        if (kt + 2 < nk) {
            issue_stage((kt + 2) % 3, (kt + 2) << 6);
            asm volatile("cp.async.wait_group 2;\n" ::: "memory");
        } else if (kt + 1 < nk) {
            asm volatile("cp.async.wait_group 1;\n" ::: "memory");
        } else {
            asm volatile("cp.async.wait_group 0;\n" ::: "memory");
        }
        __syncthreads();

        uint32_t sb = smbase + (uint32_t)(kt % 3) * STAGE2B;
        #pragma unroll
        for (int kk = 0; kk < 64; kk += 16) {
            uint32_t a[4][4], b[4][2];
            #pragma unroll
            for (int mi = 0; mi < 4; mi++)
                LDSM4(a[mi], sb + (aBase + mi * (16 * LDT2) + kk) * 2);
            #pragma unroll
            for (int h = 0; h < 2; h++) {
                uint32_t t4[4];
                LDSM4(t4, sb + TILEH2 * 2 + (bBase + h * (16 * LDT2) + kk) * 2);
                b[2*h][0] = t4[0]; b[2*h][1] = t4[1];
                b[2*h+1][0] = t4[2]; b[2*h+1][1] = t4[3];
            }
            #pragma unroll
            for (int mi = 0; mi < 4; mi++)
                #pragma unroll
                for (int nj = 0; nj < 4; nj++)
                    MMA16816(acc[mi][nj], a[mi], b[nj]);
        }
        __syncthreads();
    }

    // epilogue
    const int tr = lane >> 2, tc2 = (lane & 3) << 1;
    #pragma unroll
    for (int mi = 0; mi < 4; mi++) {
        int row = bm + wm * 64 + mi * 16 + tr;
        #pragma unroll
        for (int nj = 0; nj < 4; nj++) {
            int col = bn + wn * 32 + nj * 8 + tc2;
            float b0 = bias[col], b1 = bias[col + 1];
            *(float2*)(C + (size_t)row * DOUT + col) =
                make_float2(acc[mi][nj][0] + b0, acc[mi][nj][1] + b1);
            *(float2*)(C + (size_t)(row + 8) * DOUT + col) =
                make_float2(acc[mi][nj][2] + b0, acc[mi][nj][3] + b1);
        }
    }
}

// ---------------- launch ------------------------------------------------------
extern "C" void kernel_launch(void* const* d_in, const int* in_sizes, int n_in,
                              void* d_out, int out_size)
{
    const float* x  = (const float*)d_in[0];
    const float* bw = (const float*)d_in[1];
    const float* bb = (const float*)d_in[2];
    const float* Am = (const float*)d_in[3];
    const float* Bm = (const float*)d_in[4];
    const float* rw = (const float*)d_in[5];
    float* out = (float*)d_out;

    void *pxg, *pwt, *pw2, *phl;
    cudaGetSymbolAddress(&pxg, g_xg);
    cudaGetSymbolAddress(&pwt, g_wt);
    cudaGetSymbolAddress(&pw2, g_w2);
    cudaGetSymbolAddress(&phl, g_hl);

    cudaFuncSetAttribute(gemm128_kernel,
                         cudaFuncAttributeMaxDynamicSharedMemorySize, SMEM1);
    cudaFuncSetAttribute(gemm_main_kernel,
                         cudaFuncAttributeMaxDynamicSharedMemorySize, SMEM2);

    // merged conversions: x -> fp16, [base_w|B_flat] -> fp16, [A;router] -> fp16
    prep_all_kernel<<<NPREP / 256, 256>>>((const float4*)x, bw, Bm, Am, rw);

    // hidden + router logits: [8192,128] = x @ w2^T, split-K 8
    gemm128_kernel<<<dim3(1, 64, NSPLIT), 256, SMEM1>>>(
        (const __half*)pxg, KTOT,
        (const __half*)pw2, DIN,
        (float*)phl, 128, DIN / NSPLIT);

    router_kernel<<<M_TOK / 8, 256>>>();

    // main fused GEMM: out = [x|g] @ [base_w|B_flat]^T + bias
    gemm_main_kernel<<<dim3(DOUT / 128, M_TOK / 128), 256, SMEM2>>>(
        (const __half*)pxg, (const __half*)pwt, out, bb);
}

// round 13
// speedup vs baseline: 1.2943x; 1.0440x over previous
#include <cuda_runtime.h>
#include <cuda_fp16.h>
#include <cstdint>

#define M_TOK   8192
#define DIN     4096
#define DOUT    4096
#define RNK     64
#define NEXP    16
#define KG      1024
#define KTOT    5120
#define SCALING 0.5f
#define NSPLIT  8

// ---------------- scratch (static device globals; no allocations) -----------
__device__ __half g_xg[(size_t)M_TOK * KTOT];   // 80 MB  [x | g] fp16, row-major
__device__ __half g_wt[(size_t)DOUT * KTOT];    // 40 MB  [base_w | B_flat] fp16
__device__ __half g_w2[128 * DIN];              //  1 MB  [A; router_w; 0] fp16
__device__ float  g_hl[NSPLIT * M_TOK * 128];   // 32 MB  split-K partials (8 planes)

// ---------------- helpers ----------------------------------------------------
__device__ __forceinline__ uint32_t smem_u32(const void* p) {
    return (uint32_t)__cvta_generic_to_shared(p);
}
__device__ __forceinline__ uint32_t pack2h(__half a, __half b) {
    return (uint32_t)__half_as_ushort(a) | ((uint32_t)__half_as_ushort(b) << 16);
}
__device__ __forceinline__ uint2 cvt4(float4 v) {
    return make_uint2(pack2h(__float2half_rn(v.x), __float2half_rn(v.y)),
                      pack2h(__float2half_rn(v.z), __float2half_rn(v.w)));
}

// ---------------- merged conversion kernel ------------------------------------
#define NX   (M_TOK * DIN / 4)              // 8388608  x items
#define NW   (DOUT * KTOT / 4)              // 5242880  W items
#define NW2  (128 * DIN / 4)                // 131072   w2 items
#define NPREP (NX + NW + NW2)               // 13762560 = 53760 * 256

__global__ void prep_all_kernel(const float4* __restrict__ x4,
                                const float* __restrict__ bw,
                                const float* __restrict__ Bm,
                                const float* __restrict__ Am,
                                const float* __restrict__ rw)
{
    int i = blockIdx.x * blockDim.x + threadIdx.x;
    if (i < NX) {
        float4 v = x4[i];
        int e = i << 2;
        int row = e >> 12, col = e & (DIN - 1);
        *(uint2*)(g_xg + (size_t)row * KTOT + col) = cvt4(v);
    } else if (i < NX + NW) {
        int j = i - NX;
        int e = j << 2;
        int o = e / KTOT, k = e - o * KTOT;
        float4 v;
        if (k < DIN) {
            v = *(const float4*)(bw + (size_t)o * DIN + k);
        } else {
            int kk = k - DIN, ei = kk >> 6, r = kk & 63;
            v = *(const float4*)(Bm + ((size_t)(ei * DOUT + o) * RNK + r));
        }
        *(uint2*)(g_wt + (size_t)o * KTOT + k) = cvt4(v);
    } else {
        int j = i - NX - NW;
        int e = j << 2;
        int r = e >> 12, k = e & (DIN - 1);
        float4 v = make_float4(0.f, 0.f, 0.f, 0.f);
        if (r < 64)      v = *(const float4*)(Am + (size_t)r * DIN + k);
        else if (r < 80) v = *(const float4*)(rw + (size_t)(r - 64) * DIN + k);
        *(uint2*)(g_w2 + (size_t)r * DIN + k) = cvt4(v);
    }
}

// ---------------- router: softmax/top2 -> g columns of g_xg -------------------
__global__ void router_kernel() {
    int warp = threadIdx.x >> 5, lane = threadIdx.x & 31;
    int t = blockIdx.x * 8 + warp;
    __shared__ float wsel[8][16];
    __shared__ float hsum[8][64];
    const float* p0 = g_hl + (size_t)t * 128;

    if (lane < 16) {
        float lg = 0.f;
        #pragma unroll
        for (int s = 0; s < NSPLIT; s++) lg += p0[(size_t)s * M_TOK * 128 + 64 + lane];
        wsel[warp][lane] = lg;                     // temp: raw logits
    }
    #pragma unroll
    for (int c = lane; c < 64; c += 32) {
        float hv = 0.f;
        #pragma unroll
        for (int s = 0; s < NSPLIT; s++) hv += p0[(size_t)s * M_TOK * 128 + c];
        hsum[warp][c] = hv;
    }
    __syncwarp();
    if (lane == 0) {
        float lg[16]; float m = -1e30f;
        #pragma unroll
        for (int e = 0; e < 16; e++) { lg[e] = wsel[warp][e]; m = fmaxf(m, lg[e]); }
        float p[16], Z = 0.f;
        #pragma unroll
        for (int e = 0; e < 16; e++) { p[e] = expf(lg[e] - m); Z += p[e]; }
        float inv = 1.f / Z;
        int i1 = 0; float b1 = -1.f;
        #pragma unroll
        for (int e = 0; e < 16; e++) if (p[e] > b1) { b1 = p[e]; i1 = e; }
        int i2 = 0; float b2 = -1.f;
        #pragma unroll
        for (int e = 0; e < 16; e++) if (e != i1 && p[e] > b2) { b2 = p[e]; i2 = e; }
        b1 *= inv; b2 *= inv;
        float den = b1 + b2 + 1e-6f;
        #pragma unroll
        for (int e = 0; e < 16; e++) wsel[warp][e] = 0.f;
        wsel[warp][i1] = (b1 / den) * SCALING;
        wsel[warp][i2] = (b2 / den) * SCALING;
    }
    __syncwarp();
    __half* grow = g_xg + (size_t)t * KTOT + DIN;
    #pragma unroll
    for (int c = lane; c < KG; c += 32) {
        grow[c] = __float2half_rn(wsel[warp][c >> 6] * hsum[warp][c & 63]);
    }
}

// ---------------- common GEMM macros ------------------------------------------
#define CPASYNC(dst, src) \
    asm volatile("cp.async.cg.shared.global [%0], [%1], 16;\n" :: "r"(dst), "l"(src))
#define LDSM4(d, addr) \
    asm volatile("ldmatrix.sync.aligned.m8n8.x4.shared.b16 {%0,%1,%2,%3}, [%4];" \
        : "=r"((d)[0]), "=r"((d)[1]), "=r"((d)[2]), "=r"((d)[3]) : "r"(addr))
#define MMA16816(c, a, b) \
    asm volatile("mma.sync.aligned.m16n8k16.row.col.f32.f16.f16.f32 " \
        "{%0,%1,%2,%3}, {%4,%5,%6,%7}, {%8,%9}, {%0,%1,%2,%3};" \
        : "+f"((c)[0]), "+f"((c)[1]), "+f"((c)[2]), "+f"((c)[3]) \
        : "r"((a)[0]), "r"((a)[1]), "r"((a)[2]), "r"((a)[3]), "r"((b)[0]), "r"((b)[1]))

extern __shared__ __align__(128) unsigned char smem_buf[];

// ---------------- small GEMM: 128x128 tile, K32 chunks (split-K 8) ------------
#define LDT1     40
#define TILEH1   (128 * LDT1)
#define STAGEH1  (2 * TILEH1)
#define SMEM1    (3 * STAGEH1 * 2)          // 61440

__global__ __launch_bounds__(256, 2)
void gemm128_kernel(const __half* __restrict__ A, int lda,
                    const __half* __restrict__ B, int ldb,
                    float* __restrict__ C, int ldc, int Kdim)
{
    const int tid = threadIdx.x, lane = tid & 31, warp = tid >> 5;
    const int wm = warp >> 2, wn = warp & 3;
    const int bm = blockIdx.y << 7;
    const uint32_t smbase = smem_u32(smem_buf);

    const int koff = blockIdx.z * Kdim;
    A += koff; B += koff;
    C += (size_t)blockIdx.z * M_TOK * ldc;

    const int r0 = tid >> 2, q0 = (tid & 3) << 3, r1 = r0 + 64;
    const uint32_t ob0 = (uint32_t)(r0 * LDT1 + q0) * 2;
    const uint32_t ob1 = (uint32_t)(r1 * LDT1 + q0) * 2;

    const __half* gA0 = A + (size_t)(bm + r0) * lda + q0;
    const __half* gA1 = A + (size_t)(bm + r1) * lda + q0;
    const __half* gB0 = B + (size_t)r0 * ldb + q0;
    const __half* gB1 = B + (size_t)r1 * ldb + q0;

    auto issue_stage = [&](int st, int k0) {
        uint32_t sb = smbase + (uint32_t)st * (STAGEH1 * 2);
        CPASYNC(sb + ob0, gA0 + k0);
        CPASYNC(sb + ob1, gA1 + k0);
        CPASYNC(sb + TILEH1 * 2 + ob0, gB0 + k0);
        CPASYNC(sb + TILEH1 * 2 + ob1, gB1 + k0);
        asm volatile("cp.async.commit_group;\n" ::);
    };

    const uint32_t aBase = (uint32_t)((wm * 64 + (lane & 15)) * LDT1 + ((lane >> 4) << 3));
    const uint32_t bBase = (uint32_t)((wn * 32 + ((lane >> 4) << 3) + (lane & 7)) * LDT1
                                      + (((lane >> 3) & 1) << 3));
    float acc[4][4][4] = {};
    const int nk = Kdim >> 5;

    issue_stage(0, 0);
    if (nk > 1) issue_stage(1, 32);

    for (int kt = 0; kt < nk; kt++) {
        if (kt + 1 < nk) {
            asm volatile("cp.async.wait_group 1;\n" ::: "memory");
        } else {
            asm volatile("cp.async.wait_group 0;\n" ::: "memory");
        }
        __syncthreads();
        if (kt + 2 < nk) issue_stage((kt + 2) % 3, (kt + 2) << 5);

        uint32_t sb = smbase + (uint32_t)(kt % 3) * (STAGEH1 * 2);
        #pragma unroll
        for (int kk = 0; kk < 32; kk += 16) {
            uint32_t a[4][4], b[4][2];
            #pragma unroll
            for (int mi = 0; mi < 4; mi++)
                LDSM4(a[mi], sb + (aBase + mi * (16 * LDT1) + kk) * 2);
            #pragma unroll
            for (int h = 0; h < 2; h++) {
                uint32_t t4[4];
                LDSM4(t4, sb + TILEH1 * 2 + (bBase + h * (16 * LDT1) + kk) * 2);
                b[2*h][0] = t4[0]; b[2*h][1] = t4[1];
                b[2*h+1][0] = t4[2]; b[2*h+1][1] = t4[3];
            }
            #pragma unroll
            for (int mi = 0; mi < 4; mi++)
                #pragma unroll
                for (int nj = 0; nj < 4; nj++)
                    MMA16816(acc[mi][nj], a[mi], b[nj]);
        }
    }

    const int tr = lane >> 2, tc2 = (lane & 3) << 1;
    #pragma unroll
    for (int mi = 0; mi < 4; mi++) {
        int row = bm + wm * 64 + mi * 16 + tr;
        #pragma unroll
        for (int nj = 0; nj < 4; nj++) {
            int col = wn * 32 + nj * 8 + tc2;
            *(float2*)(C + (size_t)row * ldc + col) = make_float2(acc[mi][nj][0], acc[mi][nj][1]);
            *(float2*)(C + (size_t)(row + 8) * ldc + col) = make_float2(acc[mi][nj][2], acc[mi][nj][3]);
        }
    }
}

// ---------------- main GEMM: 128x128 block, 64x32 warp tile, K64 chunks -------
#define LDT2     72                         // 64 + 8 halves pad (144B rows)
#define TILEH2   (128 * LDT2)               // halves per tile (A or B)
#define STAGE2B  (2 * TILEH2 * 2)           // 36864 B per stage
#define SMEM2    (3 * STAGE2B)              // 110592 B (2 CTAs/SM = 221KB)

__global__ __launch_bounds__(256, 2)
void gemm_main_kernel(const __half* __restrict__ A,
                      const __half* __restrict__ B,
                      float* __restrict__ C,
                      const float* __restrict__ bias)
{
    const int tid = threadIdx.x, lane = tid & 31, warp = tid >> 5;
    const int wm = warp >> 2, wn = warp & 3;            // 2 x 4 warps, tile 64x32
    const int bm = blockIdx.y << 7, bn = blockIdx.x << 7;
    const uint32_t smbase = smem_u32(smem_buf);

    // cp.async: per stage, A and B are each 128 rows x 128B = 1024 chunks; 4/thread
    uint32_t aob[4];
    const __half *gA[4], *gB[4];
    #pragma unroll
    for (int j = 0; j < 4; j++) {
        int c = tid + 256 * j;
        int row = c >> 3, q = (c & 7) << 3;
        aob[j] = (uint32_t)(row * LDT2 + q) * 2;
        gA[j] = A + (size_t)(bm + row) * KTOT + q;
        gB[j] = B + (size_t)(bn + row) * KTOT + q;
    }

    auto issue_stage = [&](int st, int k0) {
        uint32_t sb = smbase + (uint32_t)st * STAGE2B;
        #pragma unroll
        for (int j = 0; j < 4; j++) CPASYNC(sb + aob[j], gA[j] + k0);
        uint32_t sb2 = sb + TILEH2 * 2;
        #pragma unroll
        for (int j = 0; j < 4; j++) CPASYNC(sb2 + aob[j], gB[j] + k0);
        asm volatile("cp.async.commit_group;\n" ::);
    };

    const uint32_t aBase = (uint32_t)((wm * 64 + (lane & 15)) * LDT2 + ((lane >> 4) << 3));
    const uint32_t bBase = (uint32_t)((wn * 32 + ((lane >> 4) << 3) + (lane & 7)) * LDT2
                                      + (((lane >> 3) & 1) << 3));
    float acc[4][4][4] = {};
    const int nk = KTOT >> 6;                           // 80

    issue_stage(0, 0);
    issue_stage(1, 64);

    for (int kt = 0; kt < nk; kt++) {
        if (kt + 1 < nk) {
            asm volatile("cp.async.wait_group 1;\n" ::: "memory");
        } else {
            asm volatile("cp.async.wait_group 0;\n" ::: "memory");
        }
        __syncthreads();
        if (kt + 2 < nk) issue_stage((kt + 2) % 3, (kt + 2) << 6);

        uint32_t sb = smbase + (uint32_t)(kt % 3) * STAGE2B;
        #pragma unroll
        for (int kk = 0; kk < 64; kk += 16) {
            uint32_t a[4][4], b[4][2];
            #pragma unroll
            for (int mi = 0; mi < 4; mi++)
                LDSM4(a[mi], sb + (aBase + mi * (16 * LDT2) + kk) * 2);
            #pragma unroll
            for (int h = 0; h < 2; h++) {
                uint32_t t4[4];
                LDSM4(t4, sb + TILEH2 * 2 + (bBase + h * (16 * LDT2) + kk) * 2);
                b[2*h][0] = t4[0]; b[2*h][1] = t4[1];
                b[2*h+1][0] = t4[2]; b[2*h+1][1] = t4[3];
            }
            #pragma unroll
            for (int mi = 0; mi < 4; mi++)
                #pragma unroll
                for (int nj = 0; nj < 4; nj++)
                    MMA16816(acc[mi][nj], a[mi], b[nj]);
        }
    }

    // epilogue
    const int tr = lane >> 2, tc2 = (lane & 3) << 1;
    #pragma unroll
    for (int mi = 0; mi < 4; mi++) {
        int row = bm + wm * 64 + mi * 16 + tr;
        #pragma unroll
        for (int nj = 0; nj < 4; nj++) {
            int col = bn + wn * 32 + nj * 8 + tc2;
            float b0 = bias[col], b1 = bias[col + 1];
            *(float2*)(C + (size_t)row * DOUT + col) =
                make_float2(acc[mi][nj][0] + b0, acc[mi][nj][1] + b1);
            *(float2*)(C + (size_t)(row + 8) * DOUT + col) =
                make_float2(acc[mi][nj][2] + b0, acc[mi][nj][3] + b1);
        }
    }
}

// ---------------- launch ------------------------------------------------------
extern "C" void kernel_launch(void* const* d_in, const int* in_sizes, int n_in,
                              void* d_out, int out_size)
{
    const float* x  = (const float*)d_in[0];
    const float* bw = (const float*)d_in[1];
    const float* bb = (const float*)d_in[2];
    const float* Am = (const float*)d_in[3];
    const float* Bm = (const float*)d_in[4];
    const float* rw = (const float*)d_in[5];
    float* out = (float*)d_out;

    void *pxg, *pwt, *pw2, *phl;
    cudaGetSymbolAddress(&pxg, g_xg);
    cudaGetSymbolAddress(&pwt, g_wt);
    cudaGetSymbolAddress(&pw2, g_w2);
    cudaGetSymbolAddress(&phl, g_hl);

    cudaFuncSetAttribute(gemm128_kernel,
                         cudaFuncAttributeMaxDynamicSharedMemorySize, SMEM1);
    cudaFuncSetAttribute(gemm_main_kernel,
                         cudaFuncAttributeMaxDynamicSharedMemorySize, SMEM2);

    // merged conversions: x -> fp16, [base_w|B_flat] -> fp16, [A;router] -> fp16
    prep_all_kernel<<<NPREP / 256, 256>>>((const float4*)x, bw, Bm, Am, rw);

    // hidden + router logits: [8192,128] = x @ w2^T, split-K 8
    gemm128_kernel<<<dim3(1, 64, NSPLIT), 256, SMEM1>>>(
        (const __half*)pxg, KTOT,
        (const __half*)pw2, DIN,
        (float*)phl, 128, DIN / NSPLIT);

    router_kernel<<<M_TOK / 8, 256>>>();

    // main fused GEMM: out = [x|g] @ [base_w|B_flat]^T + bias
    gemm_main_kernel<<<dim3(DOUT / 128, M_TOK / 128), 256, SMEM2>>>(
        (const __half*)pxg, (const __half*)pwt, out, bb);
}